// round 6
// baseline (speedup 1.0000x reference)
#include <cuda_runtime.h>
#include <math.h>

#define NE 200000
#define NN 50000
#define IND 16
#define ND  64
#define HID 256

// ---------------- scratch (device globals: no allocation allowed) ----------------
__device__ float g_h1[(size_t)NE * 256];    // ELU(attr @ W1 + b1)           204.8 MB
__device__ float g_h2[(size_t)NE * 1024];   // ELU(h1 @ W2 + b2)             819.2 MB
__device__ float g_agg[(size_t)NN * ND];    // NNConv scatter target
__device__ float g_act[(size_t)NN * ND];    // ELU(x_cur)
__device__ float g_nbr[(size_t)NN * ND];    // act + segment_sum(act[src])
__device__ float g_t1[(size_t)NN * HID];
__device__ float g_t2[(size_t)NN * HID];

__device__ __forceinline__ float elu(float v) {
    return v > 0.f ? v : (__expf(v) - 1.f);
}

// ---------------- small utility kernels ----------------
__global__ void k_zero(float* __restrict__ p, int n) {
    int i = blockIdx.x * blockDim.x + threadIdx.x;
    if (i < n) p[i] = 0.f;
}

__global__ void k_copy(float* __restrict__ dst, const float* __restrict__ src, int n) {
    int i = blockIdx.x * blockDim.x + threadIdx.x;
    if (i < n) dst[i] = src[i];
}

// nbr[dst] += act[src], vectorized float4 per (edge, quarter-row)
// edge_index is int32 (JAX x64 disabled downcasts int64 -> int32)
__global__ void k_scatter(const float* __restrict__ act, const int* __restrict__ ei,
                          float* __restrict__ nbr) {
    int idx = blockIdx.x * blockDim.x + threadIdx.x;
    if (idx >= NE * 16) return;
    int e = idx >> 4, q = idx & 15;
    int s = ei[e];
    int d = ei[NE + e];
    float4 v = *(const float4*)(act + (size_t)s * 64 + q * 4);
    float* p = nbr + (size_t)d * 64 + q * 4;
    atomicAdd(p + 0, v.x);
    atomicAdd(p + 1, v.y);
    atomicAdd(p + 2, v.z);
    atomicAdd(p + 3, v.w);
}

// layer-0 combine: x @ root_w + agg + root_b -> out slice 0 + act
__global__ void k_combine0(const float* __restrict__ x, const float* __restrict__ rw,
                           const float* __restrict__ rb, const float* __restrict__ agg,
                           float* __restrict__ out, float* __restrict__ act) {
    int idx = blockIdx.x * blockDim.x + threadIdx.x;
    if (idx >= NN * 64) return;
    int n = idx >> 6, o = idx & 63;
    const float* xr = x + (size_t)n * 16;
    float s = agg[idx] + rb[o];
#pragma unroll
    for (int k = 0; k < 16; k++) s += xr[k] * rw[k * 64 + o];
    out[(size_t)n * 256 + o * 4] = s;   // [N,64,4] slice l=0
    act[idx] = elu(s);
}

// ---------------- generic tiled SGEMM: C = epi(A[M,K] @ B[K,N] + bias) ----------------
// BM=BN=64, BK=16, 256 threads, 4x4 microtile.
// ACT: 0=none, 1=ELU. EPI: 0=store C only; 1 (N==64): out2[m*256+n*4+layer]=raw, C=ELU(raw)
template <int ACT, int EPI>
__global__ void __launch_bounds__(256)
k_gemm(const float* __restrict__ A, const float* __restrict__ B,
       const float* __restrict__ bias, float* __restrict__ C,
       int M, int N, int K, float* __restrict__ out2, int layer) {
    __shared__ float sA[16][68];   // [k][m] (transposed A tile)
    __shared__ float sB[16][68];   // [k][n]
    int tid = threadIdx.x;
    int tx = tid & 15, ty = tid >> 4;
    int m0 = blockIdx.y * 64, n0 = blockIdx.x * 64;
    int lr = tid >> 2, lc = tid & 3;    // A load: row (0..63), k-group (0..3)
    int br = tid >> 4, bc = tid & 15;   // B load: k-row (0..15), n-group (0..15)

    float acc[4][4] = {};
    for (int kc = 0; kc < K; kc += 16) {
        float4 av = make_float4(0.f, 0.f, 0.f, 0.f);
        if (m0 + lr < M)
            av = *(const float4*)(A + (size_t)(m0 + lr) * K + kc + lc * 4);
        float4 bv = *(const float4*)(B + (size_t)(kc + br) * N + n0 + bc * 4);
        __syncthreads();
        sA[lc * 4 + 0][lr] = av.x;
        sA[lc * 4 + 1][lr] = av.y;
        sA[lc * 4 + 2][lr] = av.z;
        sA[lc * 4 + 3][lr] = av.w;
        *(float4*)(&sB[br][bc * 4]) = bv;
        __syncthreads();
#pragma unroll
        for (int k = 0; k < 16; k++) {
            float4 a4 = *(const float4*)(&sA[k][ty * 4]);
            float4 b4 = *(const float4*)(&sB[k][tx * 4]);
            float a[4] = {a4.x, a4.y, a4.z, a4.w};
            float b[4] = {b4.x, b4.y, b4.z, b4.w};
#pragma unroll
            for (int i = 0; i < 4; i++)
#pragma unroll
                for (int j = 0; j < 4; j++) acc[i][j] = fmaf(a[i], b[j], acc[i][j]);
        }
    }

#pragma unroll
    for (int j = 0; j < 4; j++) {
        int n = n0 + tx * 4 + j;
        float bv = bias[n];
#pragma unroll
        for (int i = 0; i < 4; i++) {
            int m = m0 + ty * 4 + i;
            if (m < M) {
                float v = acc[i][j] + bv;
                if (EPI == 1) {
                    out2[(size_t)m * 256 + n * 4 + layer] = v;
                    C[(size_t)m * N + n] = elu(v);
                } else {
                    if (ACT == 1) v = elu(v);
                    C[(size_t)m * N + n] = v;
                }
            }
        }
    }
}

// ---------------- fused NNConv message kernel ----------------
// For a 64-edge tile: loop i in [0,16): pre[64,64] = h2_tile @ W3[:, i*64:(i+1)*64],
// msg[e,o] += x[src[e],i] * ELU(pre + b3); finally atomicAdd msg into agg[dst].
// Never materializes w_e.
__global__ void __launch_bounds__(256)
k_msg(const float* __restrict__ h2, const float* __restrict__ W3,
      const float* __restrict__ b3, const float* __restrict__ x,
      const int* __restrict__ ei, float* __restrict__ agg) {
    __shared__ float sA[16][68];     // h2 chunk transposed [k][e]
    __shared__ float sB[16][68];     // W3 chunk [k][o]
    __shared__ float sX[64][17];     // x[src] tile
    __shared__ int sDst[64];

    int tid = threadIdx.x;
    int tx = tid & 15, ty = tid >> 4;
    int e0 = blockIdx.x * 64;

    if (tid < 64) sDst[tid] = ei[NE + e0 + tid];
    {
        int e = tid >> 2, kg = tid & 3;
        int s = ei[e0 + e];
        float4 v = *(const float4*)(x + (size_t)s * 16 + kg * 4);
        sX[e][kg * 4 + 0] = v.x;
        sX[e][kg * 4 + 1] = v.y;
        sX[e][kg * 4 + 2] = v.z;
        sX[e][kg * 4 + 3] = v.w;
    }
    __syncthreads();

    int lr = tid >> 2, lc = tid & 3;
    int br = tid >> 4, bc = tid & 15;

    float msg[4][4] = {};
    for (int ig = 0; ig < 16; ig++) {
        float acc[4][4] = {};
        for (int kc = 0; kc < 1024; kc += 16) {
            float4 av = *(const float4*)(h2 + (size_t)(e0 + lr) * 1024 + kc + lc * 4);
            float4 bv = *(const float4*)(W3 + (size_t)(kc + br) * 1024 + ig * 64 + bc * 4);
            __syncthreads();
            sA[lc * 4 + 0][lr] = av.x;
            sA[lc * 4 + 1][lr] = av.y;
            sA[lc * 4 + 2][lr] = av.z;
            sA[lc * 4 + 3][lr] = av.w;
            *(float4*)(&sB[br][bc * 4]) = bv;
            __syncthreads();
#pragma unroll
            for (int k = 0; k < 16; k++) {
                float4 a4 = *(const float4*)(&sA[k][ty * 4]);
                float4 b4 = *(const float4*)(&sB[k][tx * 4]);
                float a[4] = {a4.x, a4.y, a4.z, a4.w};
                float b[4] = {b4.x, b4.y, b4.z, b4.w};
#pragma unroll
                for (int i = 0; i < 4; i++)
#pragma unroll
                    for (int j = 0; j < 4; j++) acc[i][j] = fmaf(a[i], b[j], acc[i][j]);
            }
        }
        // epilogue for this i-group: bias + ELU + weight by x_src[:, ig]
#pragma unroll
        for (int j = 0; j < 4; j++) {
            float bb = b3[ig * 64 + tx * 4 + j];
#pragma unroll
            for (int i = 0; i < 4; i++) {
                float v = acc[i][j] + bb;
                v = elu(v);
                msg[i][j] = fmaf(sX[ty * 4 + i][ig], v, msg[i][j]);
            }
        }
    }

#pragma unroll
    for (int i = 0; i < 4; i++) {
        int d = sDst[ty * 4 + i];
        float* p = agg + (size_t)d * 64 + tx * 4;
#pragma unroll
        for (int j = 0; j < 4; j++) atomicAdd(p + j, msg[i][j]);
    }
}

// ---------------- launch ----------------
extern "C" void kernel_launch(void* const* d_in, const int* in_sizes, int n_in,
                              void* d_out, int out_size) {
    const float* x        = (const float*)d_in[0];
    const int*   ei       = (const int*)d_in[1];    // int32 (JAX x64 disabled)
    const float* attr     = (const float*)d_in[2];
    const float* enn_w1   = (const float*)d_in[3];
    const float* enn_b1   = (const float*)d_in[4];
    const float* enn_w2   = (const float*)d_in[5];
    const float* enn_b2   = (const float*)d_in[6];
    const float* enn_w3   = (const float*)d_in[7];
    const float* enn_b3   = (const float*)d_in[8];
    const float* root_w   = (const float*)d_in[9];
    const float* root_b   = (const float*)d_in[10];
    const float* gin_w1   = (const float*)d_in[11];
    const float* gin_b1   = (const float*)d_in[12];
    const float* gin_w2   = (const float*)d_in[13];
    const float* gin_b2   = (const float*)d_in[14];
    const float* gin_w3   = (const float*)d_in[15];
    const float* gin_b3   = (const float*)d_in[16];
    float* out = (float*)d_out;

    float *h1, *h2, *agg, *act, *nbr, *t1, *t2;
    cudaGetSymbolAddress((void**)&h1, g_h1);
    cudaGetSymbolAddress((void**)&h2, g_h2);
    cudaGetSymbolAddress((void**)&agg, g_agg);
    cudaGetSymbolAddress((void**)&act, g_act);
    cudaGetSymbolAddress((void**)&nbr, g_nbr);
    cudaGetSymbolAddress((void**)&t1, g_t1);
    cudaGetSymbolAddress((void**)&t2, g_t2);

    const int THREADS = 256;
    int gy_E = NE / 64;              // 3125 (exact)
    int gy_N = (NN + 63) / 64;       // 782

    // ---- Layer 0: NNConv ----
    // h1 = ELU(attr @ enn_w1 + b1)   [E,256]
    k_gemm<1, 0><<<dim3(256 / 64, gy_E), THREADS>>>(attr, enn_w1, enn_b1, h1,
                                                    NE, 256, 16, nullptr, 0);
    // h2 = ELU(h1 @ enn_w2 + b2)     [E,1024]
    k_gemm<1, 0><<<dim3(1024 / 64, gy_E), THREADS>>>(h1, enn_w2, enn_b2, h2,
                                                     NE, 1024, 256, nullptr, 0);
    // agg = 0
    k_zero<<<(NN * 64 + THREADS - 1) / THREADS, THREADS>>>(agg, NN * 64);
    // fused: we = ELU(h2 @ enn_w3 + b3); msg = x_src . we; agg[dst] += msg
    k_msg<<<NE / 64, THREADS>>>(h2, enn_w3, enn_b3, x, ei, agg);
    // x_cur = x @ root_w + agg + root_b ; out[:, :, 0]; act = ELU(x_cur)
    k_combine0<<<(NN * 64 + THREADS - 1) / THREADS, THREADS>>>(x, root_w, root_b,
                                                               agg, out, act);

    // ---- Layers 1..3: GINConv ----
    for (int l = 0; l < 3; l++) {
        // nbr = act ; nbr[dst] += act[src]  ->  hin = x_in + sum_j x_j
        k_copy<<<(NN * 64 + THREADS - 1) / THREADS, THREADS>>>(nbr, act, NN * 64);
        k_scatter<<<(NE * 16 + THREADS - 1) / THREADS, THREADS>>>(act, ei, nbr);
        // t1 = ELU(hin @ gin_w1[l] + gin_b1[l])     [N,256]
        k_gemm<1, 0><<<dim3(256 / 64, gy_N), THREADS>>>(nbr, gin_w1 + (size_t)l * 64 * 256,
                                                        gin_b1 + l * 256, t1,
                                                        NN, 256, 64, nullptr, 0);
        // t2 = ELU(t1 @ gin_w2[l] + gin_b2[l])      [N,256]
        k_gemm<1, 0><<<dim3(256 / 64, gy_N), THREADS>>>(t1, gin_w2 + (size_t)l * 256 * 256,
                                                        gin_b2 + l * 256, t2,
                                                        NN, 256, 256, nullptr, 0);
        // x_cur = t2 @ gin_w3[l] + gin_b3[l]; out[:, :, l+1] = x_cur; act = ELU(x_cur)
        k_gemm<0, 1><<<dim3(1, gy_N), THREADS>>>(t2, gin_w3 + (size_t)l * 256 * 64,
                                                 gin_b3 + l * 64, act,
                                                 NN, 64, 256, out, l + 1);
    }
}

// round 7
// speedup vs baseline: 1.0768x; 1.0768x over previous
#include <cuda_runtime.h>
#include <math.h>

#define NE  200000
#define NEP 200064              // 1563 * 128 (padded edge rows)
#define NN  50000
#define ND  64
#define HID 256

// ---------------- scratch (device globals; zero-initialized) ----------------
__device__ float g_h1[(size_t)NEP * 256];    // ELU(attr @ W1 + b1), pad rows stay 0
__device__ float g_h2[(size_t)NEP * 1024];   // ELU(h1 @ W2 + b2)
__device__ float g_agg[(size_t)NN * ND];
__device__ float g_act[(size_t)NN * ND];
__device__ float g_nbr[(size_t)NN * ND];
__device__ float g_t1[(size_t)NN * HID];
__device__ float g_t2[(size_t)NN * HID];

__device__ __forceinline__ float elu(float v) {
    return v > 0.f ? v : (__expf(v) - 1.f);
}

// packed f32x2 helpers (SASS FFMA2 path — PTX-only per B300 notes)
__device__ __forceinline__ void fma2(unsigned long long& d, unsigned long long a,
                                     unsigned long long b) {
    asm("fma.rn.f32x2 %0, %1, %2, %0;" : "+l"(d) : "l"(a), "l"(b));
}
__device__ __forceinline__ void unpack2(unsigned long long v, float& lo, float& hi) {
    asm("mov.b64 {%0, %1}, %2;" : "=f"(lo), "=f"(hi) : "l"(v));
}

// ---------------- small utility kernels ----------------
__global__ void k_zero(float* __restrict__ p, int n) {
    int i = blockIdx.x * blockDim.x + threadIdx.x;
    if (i < n) p[i] = 0.f;
}
__global__ void k_copy(float* __restrict__ dst, const float* __restrict__ src, int n) {
    int i = blockIdx.x * blockDim.x + threadIdx.x;
    if (i < n) dst[i] = src[i];
}
__global__ void k_scatter(const float* __restrict__ act, const int* __restrict__ ei,
                          float* __restrict__ nbr) {
    int idx = blockIdx.x * blockDim.x + threadIdx.x;
    if (idx >= NE * 16) return;
    int e = idx >> 4, q = idx & 15;
    int s = ei[e];
    int d = ei[NE + e];
    float4 v = *(const float4*)(act + (size_t)s * 64 + q * 4);
    float* p = nbr + (size_t)d * 64 + q * 4;
    atomicAdd(p + 0, v.x);
    atomicAdd(p + 1, v.y);
    atomicAdd(p + 2, v.z);
    atomicAdd(p + 3, v.w);
}
__global__ void k_combine0(const float* __restrict__ x, const float* __restrict__ rw,
                           const float* __restrict__ rb, const float* __restrict__ agg,
                           float* __restrict__ out, float* __restrict__ act) {
    int idx = blockIdx.x * blockDim.x + threadIdx.x;
    if (idx >= NN * 64) return;
    int n = idx >> 6, o = idx & 63;
    const float* xr = x + (size_t)n * 16;
    float s = agg[idx] + rb[o];
#pragma unroll
    for (int k = 0; k < 16; k++) s += xr[k] * rw[k * 64 + o];
    out[(size_t)n * 256 + o * 4] = s;   // [N,64,4] slice l=0
    act[idx] = elu(s);
}

// ---------------- generic tiled SGEMM (64x64x16) for the small GEMMs ----------------
// ACT: 0=none, 1=ELU. EPI: 0=store C; 1 (N==64): out2[m*256+n*4+layer]=raw, C=ELU(raw)
template <int ACT, int EPI>
__global__ void __launch_bounds__(256)
k_gemm(const float* __restrict__ A, const float* __restrict__ B,
       const float* __restrict__ bias, float* __restrict__ C,
       int M, int N, int K, float* __restrict__ out2, int layer) {
    __shared__ float sA[16][68];
    __shared__ float sB[16][68];
    int tid = threadIdx.x;
    int tx = tid & 15, ty = tid >> 4;
    int m0 = blockIdx.y * 64, n0 = blockIdx.x * 64;
    int lr = tid >> 2, lc = tid & 3;
    int br = tid >> 4, bc = tid & 15;

    float acc[4][4] = {};
    for (int kc = 0; kc < K; kc += 16) {
        float4 av = make_float4(0.f, 0.f, 0.f, 0.f);
        if (m0 + lr < M)
            av = *(const float4*)(A + (size_t)(m0 + lr) * K + kc + lc * 4);
        float4 bv = *(const float4*)(B + (size_t)(kc + br) * N + n0 + bc * 4);
        __syncthreads();
        sA[lc * 4 + 0][lr] = av.x;
        sA[lc * 4 + 1][lr] = av.y;
        sA[lc * 4 + 2][lr] = av.z;
        sA[lc * 4 + 3][lr] = av.w;
        *(float4*)(&sB[br][bc * 4]) = bv;
        __syncthreads();
#pragma unroll
        for (int k = 0; k < 16; k++) {
            float4 a4 = *(const float4*)(&sA[k][ty * 4]);
            float4 b4 = *(const float4*)(&sB[k][tx * 4]);
            float a[4] = {a4.x, a4.y, a4.z, a4.w};
            float b[4] = {b4.x, b4.y, b4.z, b4.w};
#pragma unroll
            for (int i = 0; i < 4; i++)
#pragma unroll
                for (int j = 0; j < 4; j++) acc[i][j] = fmaf(a[i], b[j], acc[i][j]);
        }
    }
#pragma unroll
    for (int j = 0; j < 4; j++) {
        int n = n0 + tx * 4 + j;
        float bv = bias[n];
#pragma unroll
        for (int i = 0; i < 4; i++) {
            int m = m0 + ty * 4 + i;
            if (m < M) {
                float v = acc[i][j] + bv;
                if (EPI == 1) {
                    out2[(size_t)m * 256 + n * 4 + layer] = v;
                    C[(size_t)m * N + n] = elu(v);
                } else {
                    if (ACT == 1) v = elu(v);
                    C[(size_t)m * N + n] = v;
                }
            }
        }
    }
}

// ---------------- big kernel: 128x128x8 tiles, 8x8 microtile, f32x2 FMAs ----------------
// A: [NEP, KTOT] row-major (padded scratch). B: [KTOT, 1024] row-major. N fixed = 1024.
// MSG=0: C[r*1024 + c] = ELU(acc + bias[c])   (h2 production)
// MSG=1: per 64-col group (i = c>>6, o = c&63): msg[r,o] += x[src[r],i]*ELU(acc+bias[c]);
//        atomicAdd into agg[dst[r]*64 + o]. Block covers 2 i-groups; merged before RED.
#define SAS 264   // sA row stride (floats): 256 duplicated + 8 pad
#define SBS 132   // sB row stride (floats): 128 + 4 pad
template <int KTOT, int MSG>
__global__ void __launch_bounds__(256)
k_big(const float* __restrict__ A, const float* __restrict__ B,
      const float* __restrict__ bias, float* __restrict__ C,
      const float* __restrict__ x, const int* __restrict__ ei,
      float* __restrict__ agg) {
    __shared__ float sA[2][8][SAS];   // duplicated: sA[k][2m] = sA[k][2m+1] = A[m]
    __shared__ float sB[2][8][SBS];
    __shared__ float sXlo[128], sXhi[128];
    __shared__ int sDst[128];

    int tid = threadIdx.x;
    int e0 = blockIdx.y * 128;
    int c0 = blockIdx.x * 128;

    if (MSG) {
        if (tid < 128) {
            int e = e0 + tid;
            int s = 0, d = -1;
            if (e < NE) { s = ei[e]; d = ei[NE + e]; }
            float2 xv = *(const float2*)(x + (size_t)s * 16 + (c0 >> 6));
            sXlo[tid] = xv.x;
            sXhi[tid] = xv.y;
            sDst[tid] = d;
        }
    }

    // loader roles
    int arow = tid >> 1, akq = (tid & 1) * 4;       // A: 128 rows x 8 k, float4 along K
    int bkr = tid >> 5, bnq = (tid & 31) * 4;       // B: 8 k-rows x 128 n, float4 along N
    const float* Aptr = A + (size_t)(e0 + arow) * KTOT + akq;
    const float* Bbase = B + c0 + bnq;

    float4 a_ld = *(const float4*)(Aptr);
    float4 b_ld = *(const float4*)(Bbase + (size_t)bkr * 1024);

    int tx = tid & 15, ty = tid >> 4;
    unsigned long long acc[8][4];
#pragma unroll
    for (int i = 0; i < 8; i++)
#pragma unroll
        for (int j = 0; j < 4; j++) acc[i][j] = 0ull;

    int buf = 0;
    // stage 0 store
    {
        sA[0][akq + 0][2 * arow] = a_ld.x; sA[0][akq + 0][2 * arow + 1] = a_ld.x;
        sA[0][akq + 1][2 * arow] = a_ld.y; sA[0][akq + 1][2 * arow + 1] = a_ld.y;
        sA[0][akq + 2][2 * arow] = a_ld.z; sA[0][akq + 2][2 * arow + 1] = a_ld.z;
        sA[0][akq + 3][2 * arow] = a_ld.w; sA[0][akq + 3][2 * arow + 1] = a_ld.w;
        *(float4*)(&sB[0][bkr][bnq]) = b_ld;
    }
    __syncthreads();

    const int NSTAGE = KTOT / 8;
#pragma unroll 1
    for (int s = 1; s < NSTAGE; s++) {
        a_ld = *(const float4*)(Aptr + s * 8);
        b_ld = *(const float4*)(Bbase + (size_t)(s * 8 + bkr) * 1024);
#pragma unroll
        for (int k = 0; k < 8; k++) {
            ulonglong2 a01 = *(const ulonglong2*)(&sA[buf][k][(ty * 8 + 0) * 2]);
            ulonglong2 a23 = *(const ulonglong2*)(&sA[buf][k][(ty * 8 + 2) * 2]);
            ulonglong2 a45 = *(const ulonglong2*)(&sA[buf][k][(ty * 8 + 4) * 2]);
            ulonglong2 a67 = *(const ulonglong2*)(&sA[buf][k][(ty * 8 + 6) * 2]);
            ulonglong2 blo = *(const ulonglong2*)(&sB[buf][k][tx * 4]);
            ulonglong2 bhi = *(const ulonglong2*)(&sB[buf][k][64 + tx * 4]);
            fma2(acc[0][0], a01.x, blo.x); fma2(acc[0][1], a01.x, blo.y);
            fma2(acc[0][2], a01.x, bhi.x); fma2(acc[0][3], a01.x, bhi.y);
            fma2(acc[1][0], a01.y, blo.x); fma2(acc[1][1], a01.y, blo.y);
            fma2(acc[1][2], a01.y, bhi.x); fma2(acc[1][3], a01.y, bhi.y);
            fma2(acc[2][0], a23.x, blo.x); fma2(acc[2][1], a23.x, blo.y);
            fma2(acc[2][2], a23.x, bhi.x); fma2(acc[2][3], a23.x, bhi.y);
            fma2(acc[3][0], a23.y, blo.x); fma2(acc[3][1], a23.y, blo.y);
            fma2(acc[3][2], a23.y, bhi.x); fma2(acc[3][3], a23.y, bhi.y);
            fma2(acc[4][0], a45.x, blo.x); fma2(acc[4][1], a45.x, blo.y);
            fma2(acc[4][2], a45.x, bhi.x); fma2(acc[4][3], a45.x, bhi.y);
            fma2(acc[5][0], a45.y, blo.x); fma2(acc[5][1], a45.y, blo.y);
            fma2(acc[5][2], a45.y, bhi.x); fma2(acc[5][3], a45.y, bhi.y);
            fma2(acc[6][0], a67.x, blo.x); fma2(acc[6][1], a67.x, blo.y);
            fma2(acc[6][2], a67.x, bhi.x); fma2(acc[6][3], a67.x, bhi.y);
            fma2(acc[7][0], a67.y, blo.x); fma2(acc[7][1], a67.y, blo.y);
            fma2(acc[7][2], a67.y, bhi.x); fma2(acc[7][3], a67.y, bhi.y);
        }
        int nb = buf ^ 1;
        sA[nb][akq + 0][2 * arow] = a_ld.x; sA[nb][akq + 0][2 * arow + 1] = a_ld.x;
        sA[nb][akq + 1][2 * arow] = a_ld.y; sA[nb][akq + 1][2 * arow + 1] = a_ld.y;
        sA[nb][akq + 2][2 * arow] = a_ld.z; sA[nb][akq + 2][2 * arow + 1] = a_ld.z;
        sA[nb][akq + 3][2 * arow] = a_ld.w; sA[nb][akq + 3][2 * arow + 1] = a_ld.w;
        *(float4*)(&sB[nb][bkr][bnq]) = b_ld;
        __syncthreads();
        buf = nb;
    }
    // last stage compute
#pragma unroll
    for (int k = 0; k < 8; k++) {
        ulonglong2 a01 = *(const ulonglong2*)(&sA[buf][k][(ty * 8 + 0) * 2]);
        ulonglong2 a23 = *(const ulonglong2*)(&sA[buf][k][(ty * 8 + 2) * 2]);
        ulonglong2 a45 = *(const ulonglong2*)(&sA[buf][k][(ty * 8 + 4) * 2]);
        ulonglong2 a67 = *(const ulonglong2*)(&sA[buf][k][(ty * 8 + 6) * 2]);
        ulonglong2 blo = *(const ulonglong2*)(&sB[buf][k][tx * 4]);
        ulonglong2 bhi = *(const ulonglong2*)(&sB[buf][k][64 + tx * 4]);
        fma2(acc[0][0], a01.x, blo.x); fma2(acc[0][1], a01.x, blo.y);
        fma2(acc[0][2], a01.x, bhi.x); fma2(acc[0][3], a01.x, bhi.y);
        fma2(acc[1][0], a01.y, blo.x); fma2(acc[1][1], a01.y, blo.y);
        fma2(acc[1][2], a01.y, bhi.x); fma2(acc[1][3], a01.y, bhi.y);
        fma2(acc[2][0], a23.x, blo.x); fma2(acc[2][1], a23.x, blo.y);
        fma2(acc[2][2], a23.x, bhi.x); fma2(acc[2][3], a23.x, bhi.y);
        fma2(acc[3][0], a23.y, blo.x); fma2(acc[3][1], a23.y, blo.y);
        fma2(acc[3][2], a23.y, bhi.x); fma2(acc[3][3], a23.y, bhi.y);
        fma2(acc[4][0], a45.x, blo.x); fma2(acc[4][1], a45.x, blo.y);
        fma2(acc[4][2], a45.x, bhi.x); fma2(acc[4][3], a45.x, bhi.y);
        fma2(acc[5][0], a45.y, blo.x); fma2(acc[5][1], a45.y, blo.y);
        fma2(acc[5][2], a45.y, bhi.x); fma2(acc[5][3], a45.y, bhi.y);
        fma2(acc[6][0], a67.x, blo.x); fma2(acc[6][1], a67.x, blo.y);
        fma2(acc[6][2], a67.x, bhi.x); fma2(acc[6][3], a67.x, bhi.y);
        fma2(acc[7][0], a67.y, blo.x); fma2(acc[7][1], a67.y, blo.y);
        fma2(acc[7][2], a67.y, bhi.x); fma2(acc[7][3], a67.y, bhi.y);
    }

    // ---- epilogue ----
    float bl0 = bias[c0 + tx * 4 + 0], bl1 = bias[c0 + tx * 4 + 1];
    float bl2 = bias[c0 + tx * 4 + 2], bl3 = bias[c0 + tx * 4 + 3];
    float bh0 = bias[c0 + 64 + tx * 4 + 0], bh1 = bias[c0 + 64 + tx * 4 + 1];
    float bh2 = bias[c0 + 64 + tx * 4 + 2], bh3 = bias[c0 + 64 + tx * 4 + 3];

#pragma unroll
    for (int i = 0; i < 8; i++) {
        int r = ty * 8 + i;
        float l0, l1, l2, l3, h0, h1, h2, h3;
        unpack2(acc[i][0], l0, l1);
        unpack2(acc[i][1], l2, l3);
        unpack2(acc[i][2], h0, h1);
        unpack2(acc[i][3], h2, h3);
        l0 = elu(l0 + bl0); l1 = elu(l1 + bl1); l2 = elu(l2 + bl2); l3 = elu(l3 + bl3);
        h0 = elu(h0 + bh0); h1 = elu(h1 + bh1); h2 = elu(h2 + bh2); h3 = elu(h3 + bh3);
        if (MSG) {
            float xlo = sXlo[r], xhi = sXhi[r];
            int d = sDst[r];
            if (d >= 0) {
                float* p = agg + (size_t)d * 64 + tx * 4;
                atomicAdd(p + 0, fmaf(xlo, l0, xhi * h0));
                atomicAdd(p + 1, fmaf(xlo, l1, xhi * h1));
                atomicAdd(p + 2, fmaf(xlo, l2, xhi * h2));
                atomicAdd(p + 3, fmaf(xlo, l3, xhi * h3));
            }
        } else {
            float* cp = C + (size_t)(e0 + r) * 1024 + c0;
            *(float4*)(cp + tx * 4) = make_float4(l0, l1, l2, l3);
            *(float4*)(cp + 64 + tx * 4) = make_float4(h0, h1, h2, h3);
        }
    }
}

// ---------------- launch ----------------
extern "C" void kernel_launch(void* const* d_in, const int* in_sizes, int n_in,
                              void* d_out, int out_size) {
    const float* x      = (const float*)d_in[0];
    const int*   ei     = (const int*)d_in[1];
    const float* attr   = (const float*)d_in[2];
    const float* enn_w1 = (const float*)d_in[3];
    const float* enn_b1 = (const float*)d_in[4];
    const float* enn_w2 = (const float*)d_in[5];
    const float* enn_b2 = (const float*)d_in[6];
    const float* enn_w3 = (const float*)d_in[7];
    const float* enn_b3 = (const float*)d_in[8];
    const float* root_w = (const float*)d_in[9];
    const float* root_b = (const float*)d_in[10];
    const float* gin_w1 = (const float*)d_in[11];
    const float* gin_b1 = (const float*)d_in[12];
    const float* gin_w2 = (const float*)d_in[13];
    const float* gin_b2 = (const float*)d_in[14];
    const float* gin_w3 = (const float*)d_in[15];
    const float* gin_b3 = (const float*)d_in[16];
    float* out = (float*)d_out;

    float *h1, *h2, *agg, *act, *nbr, *t1, *t2;
    cudaGetSymbolAddress((void**)&h1, g_h1);
    cudaGetSymbolAddress((void**)&h2, g_h2);
    cudaGetSymbolAddress((void**)&agg, g_agg);
    cudaGetSymbolAddress((void**)&act, g_act);
    cudaGetSymbolAddress((void**)&nbr, g_nbr);
    cudaGetSymbolAddress((void**)&t1, g_t1);
    cudaGetSymbolAddress((void**)&t2, g_t2);

    const int THREADS = 256;
    int gy_N = (NN + 63) / 64;

    // ---- Layer 0: NNConv ----
    // h1 = ELU(attr @ enn_w1 + b1)   [E,256]   (pad rows of g_h1 stay zero)
    k_gemm<1, 0><<<dim3(4, (NE + 63) / 64), THREADS>>>(attr, enn_w1, enn_b1, h1,
                                                       NE, 256, 16, nullptr, 0);
    // h2 = ELU(h1 @ enn_w2 + b2)     [NEP,1024] (pad rows computed from zeros: harmless)
    k_big<256, 0><<<dim3(8, NEP / 128), THREADS>>>(h1, enn_w2, enn_b2, h2,
                                                   nullptr, nullptr, nullptr);
    k_zero<<<(NN * 64 + THREADS - 1) / THREADS, THREADS>>>(agg, NN * 64);
    // fused: we = ELU(h2 @ enn_w3 + b3); msg = x_src . we; agg[dst] += msg
    k_big<1024, 1><<<dim3(8, NEP / 128), THREADS>>>(h2, enn_w3, enn_b3, nullptr,
                                                    x, ei, agg);
    k_combine0<<<(NN * 64 + THREADS - 1) / THREADS, THREADS>>>(x, root_w, root_b,
                                                               agg, out, act);

    // ---- Layers 1..3: GINConv ----
    for (int l = 0; l < 3; l++) {
        k_copy<<<(NN * 64 + THREADS - 1) / THREADS, THREADS>>>(nbr, act, NN * 64);
        k_scatter<<<(NE * 16 + THREADS - 1) / THREADS, THREADS>>>(act, ei, nbr);
        k_gemm<1, 0><<<dim3(4, gy_N), THREADS>>>(nbr, gin_w1 + (size_t)l * 64 * 256,
                                                 gin_b1 + l * 256, t1,
                                                 NN, 256, 64, nullptr, 0);
        k_gemm<1, 0><<<dim3(4, gy_N), THREADS>>>(t1, gin_w2 + (size_t)l * 256 * 256,
                                                 gin_b2 + l * 256, t2,
                                                 NN, 256, 256, nullptr, 0);
        k_gemm<0, 1><<<dim3(1, gy_N), THREADS>>>(t2, gin_w3 + (size_t)l * 256 * 64,
                                                 gin_b3 + l * 64, act,
                                                 NN, 64, 256, out, l + 1);
    }
}

// round 10
// speedup vs baseline: 1.2200x; 1.1330x over previous
#include <cuda_runtime.h>
#include <math.h>

#define NE  200000
#define NEP 200064              // 1563 * 128 (padded edge rows)
#define NN  50000
#define ND  64
#define HID 256

// ---------------- scratch (device globals; zero-initialized) ----------------
__device__ float g_h1[(size_t)NEP * 256];    // ELU(attr @ W1 + b1), pad rows stay 0
__device__ float g_h2[(size_t)NEP * 1024];   // ELU(h1 @ W2 + b2)
__device__ float g_agg[(size_t)NN * ND];
__device__ float g_act[(size_t)NN * ND];
__device__ float g_nbr[(size_t)NN * ND];
__device__ float g_t1[(size_t)NN * HID];
__device__ float g_t2[(size_t)NN * HID];

__device__ __forceinline__ float elu(float v) {
    return v > 0.f ? v : (__expf(v) - 1.f);
}

// packed f32x2 helpers (SASS FFMA2 path — PTX-only per B300 notes)
__device__ __forceinline__ void fma2(unsigned long long& d, unsigned long long a,
                                     unsigned long long b) {
    asm("fma.rn.f32x2 %0, %1, %2, %0;" : "+l"(d) : "l"(a), "l"(b));
}
__device__ __forceinline__ void unpack2(unsigned long long v, float& lo, float& hi) {
    asm("mov.b64 {%0, %1}, %2;" : "=f"(lo), "=f"(hi) : "l"(v));
}

// ---------------- small utility kernels ----------------
__global__ void k_zero(float* __restrict__ p, int n) {
    int i = blockIdx.x * blockDim.x + threadIdx.x;
    if (i < n) p[i] = 0.f;
}
__global__ void k_copy(float* __restrict__ dst, const float* __restrict__ src, int n) {
    int i = blockIdx.x * blockDim.x + threadIdx.x;
    if (i < n) dst[i] = src[i];
}
__global__ void k_scatter(const float* __restrict__ act, const int* __restrict__ ei,
                          float* __restrict__ nbr) {
    int idx = blockIdx.x * blockDim.x + threadIdx.x;
    if (idx >= NE * 16) return;
    int e = idx >> 4, q = idx & 15;
    int s = ei[e];
    int d = ei[NE + e];
    float4 v = *(const float4*)(act + (size_t)s * 64 + q * 4);
    float* p = nbr + (size_t)d * 64 + q * 4;
    atomicAdd(p + 0, v.x);
    atomicAdd(p + 1, v.y);
    atomicAdd(p + 2, v.z);
    atomicAdd(p + 3, v.w);
}
__global__ void k_combine0(const float* __restrict__ x, const float* __restrict__ rw,
                           const float* __restrict__ rb, const float* __restrict__ agg,
                           float* __restrict__ out, float* __restrict__ act) {
    int idx = blockIdx.x * blockDim.x + threadIdx.x;
    if (idx >= NN * 64) return;
    int n = idx >> 6, o = idx & 63;
    const float* xr = x + (size_t)n * 16;
    float s = agg[idx] + rb[o];
#pragma unroll
    for (int k = 0; k < 16; k++) s += xr[k] * rw[k * 64 + o];
    out[(size_t)n * 256 + o * 4] = s;   // [N,64,4] slice l=0
    act[idx] = elu(s);
}

// ---------------- generic tiled SGEMM (64x64x16) for the small GEMMs ----------------
// ACT: 0=none, 1=ELU. EPI: 0=store C; 1 (N==64): out2[m*256+n*4+layer]=raw, C=ELU(raw)
template <int ACT, int EPI>
__global__ void __launch_bounds__(256)
k_gemm(const float* __restrict__ A, const float* __restrict__ B,
       const float* __restrict__ bias, float* __restrict__ C,
       int M, int N, int K, float* __restrict__ out2, int layer) {
    __shared__ float sA[16][68];
    __shared__ float sB[16][68];
    int tid = threadIdx.x;
    int tx = tid & 15, ty = tid >> 4;
    int m0 = blockIdx.y * 64, n0 = blockIdx.x * 64;
    int lr = tid >> 2, lc = tid & 3;
    int br = tid >> 4, bc = tid & 15;

    float acc[4][4] = {};
    for (int kc = 0; kc < K; kc += 16) {
        float4 av = make_float4(0.f, 0.f, 0.f, 0.f);
        if (m0 + lr < M)
            av = *(const float4*)(A + (size_t)(m0 + lr) * K + kc + lc * 4);
        float4 bv = *(const float4*)(B + (size_t)(kc + br) * N + n0 + bc * 4);
        __syncthreads();
        sA[lc * 4 + 0][lr] = av.x;
        sA[lc * 4 + 1][lr] = av.y;
        sA[lc * 4 + 2][lr] = av.z;
        sA[lc * 4 + 3][lr] = av.w;
        *(float4*)(&sB[br][bc * 4]) = bv;
        __syncthreads();
#pragma unroll
        for (int k = 0; k < 16; k++) {
            float4 a4 = *(const float4*)(&sA[k][ty * 4]);
            float4 b4 = *(const float4*)(&sB[k][tx * 4]);
            float a[4] = {a4.x, a4.y, a4.z, a4.w};
            float b[4] = {b4.x, b4.y, b4.z, b4.w};
#pragma unroll
            for (int i = 0; i < 4; i++)
#pragma unroll
                for (int j = 0; j < 4; j++) acc[i][j] = fmaf(a[i], b[j], acc[i][j]);
        }
    }
#pragma unroll
    for (int j = 0; j < 4; j++) {
        int n = n0 + tx * 4 + j;
        float bv = bias[n];
#pragma unroll
        for (int i = 0; i < 4; i++) {
            int m = m0 + ty * 4 + i;
            if (m < M) {
                float v = acc[i][j] + bv;
                if (EPI == 1) {
                    out2[(size_t)m * 256 + n * 4 + layer] = v;
                    C[(size_t)m * N + n] = elu(v);
                } else {
                    if (ACT == 1) v = elu(v);
                    C[(size_t)m * N + n] = v;
                }
            }
        }
    }
}

// ---------------- big kernel: 128x128x8 tiles, 8x8 microtile, f32x2 FMAs ----------------
// __launch_bounds__(256, 2): cap regs at 128 so 2 CTAs/SM co-reside (occ 12.5% -> 25%).
// A: [NEP, KTOT] row-major (padded scratch). B: [KTOT, 1024] row-major. N fixed = 1024.
// MSG=0: C[r*1024 + c] = ELU(acc + bias[c])   (h2 production)
// MSG=1: per 64-col group (i = c>>6, o = c&63): msg[r,o] += x[src[r],i]*ELU(acc+bias[c]);
//        atomicAdd into agg[dst[r]*64 + o]. Block covers 2 i-groups; merged before RED.
#define SAS 264   // sA row stride (floats): 256 duplicated + 8 pad
#define SBS 132   // sB row stride (floats): 128 + 4 pad
template <int KTOT, int MSG>
__global__ void __launch_bounds__(256, 2)
k_big(const float* __restrict__ A, const float* __restrict__ B,
      const float* __restrict__ bias, float* __restrict__ C,
      const float* __restrict__ x, const int* __restrict__ ei,
      float* __restrict__ agg) {
    __shared__ float sA[2][8][SAS];   // duplicated: sA[k][2m] = sA[k][2m+1] = A[m]
    __shared__ float sB[2][8][SBS];
    __shared__ float sXlo[128], sXhi[128];
    __shared__ int sDst[128];

    int tid = threadIdx.x;
    int e0 = blockIdx.y * 128;
    int c0 = blockIdx.x * 128;

    if (MSG) {
        if (tid < 128) {
            int e = e0 + tid;
            int s = 0, d = -1;
            if (e < NE) { s = ei[e]; d = ei[NE + e]; }
            float2 xv = *(const float2*)(x + (size_t)s * 16 + (c0 >> 6));
            sXlo[tid] = xv.x;
            sXhi[tid] = xv.y;
            sDst[tid] = d;
        }
    }

    // loader roles
    int arow = tid >> 1, akq = (tid & 1) * 4;       // A: 128 rows x 8 k, float4 along K
    int bkr = tid >> 5, bnq = (tid & 31) * 4;       // B: 8 k-rows x 128 n, float4 along N
    const float* Aptr = A + (size_t)(e0 + arow) * KTOT + akq;
    const float* Bbase = B + c0 + bnq;

    float4 a_ld = *(const float4*)(Aptr);
    float4 b_ld = *(const float4*)(Bbase + (size_t)bkr * 1024);

    int tx = tid & 15, ty = tid >> 4;
    unsigned long long acc[8][4];
#pragma unroll
    for (int i = 0; i < 8; i++)
#pragma unroll
        for (int j = 0; j < 4; j++) acc[i][j] = 0ull;

    int buf = 0;
    // stage 0 store
    {
        sA[0][akq + 0][2 * arow] = a_ld.x; sA[0][akq + 0][2 * arow + 1] = a_ld.x;
        sA[0][akq + 1][2 * arow] = a_ld.y; sA[0][akq + 1][2 * arow + 1] = a_ld.y;
        sA[0][akq + 2][2 * arow] = a_ld.z; sA[0][akq + 2][2 * arow + 1] = a_ld.z;
        sA[0][akq + 3][2 * arow] = a_ld.w; sA[0][akq + 3][2 * arow + 1] = a_ld.w;
        *(float4*)(&sB[0][bkr][bnq]) = b_ld;
    }
    __syncthreads();

    const int NSTAGE = KTOT / 8;
#pragma unroll 1
    for (int s = 1; s < NSTAGE; s++) {
        a_ld = *(const float4*)(Aptr + s * 8);
        b_ld = *(const float4*)(Bbase + (size_t)(s * 8 + bkr) * 1024);
#pragma unroll
        for (int k = 0; k < 8; k++) {
            ulonglong2 a01 = *(const ulonglong2*)(&sA[buf][k][(ty * 8 + 0) * 2]);
            ulonglong2 a23 = *(const ulonglong2*)(&sA[buf][k][(ty * 8 + 2) * 2]);
            ulonglong2 a45 = *(const ulonglong2*)(&sA[buf][k][(ty * 8 + 4) * 2]);
            ulonglong2 a67 = *(const ulonglong2*)(&sA[buf][k][(ty * 8 + 6) * 2]);
            ulonglong2 blo = *(const ulonglong2*)(&sB[buf][k][tx * 4]);
            ulonglong2 bhi = *(const ulonglong2*)(&sB[buf][k][64 + tx * 4]);
            fma2(acc[0][0], a01.x, blo.x); fma2(acc[0][1], a01.x, blo.y);
            fma2(acc[0][2], a01.x, bhi.x); fma2(acc[0][3], a01.x, bhi.y);
            fma2(acc[1][0], a01.y, blo.x); fma2(acc[1][1], a01.y, blo.y);
            fma2(acc[1][2], a01.y, bhi.x); fma2(acc[1][3], a01.y, bhi.y);
            fma2(acc[2][0], a23.x, blo.x); fma2(acc[2][1], a23.x, blo.y);
            fma2(acc[2][2], a23.x, bhi.x); fma2(acc[2][3], a23.x, bhi.y);
            fma2(acc[3][0], a23.y, blo.x); fma2(acc[3][1], a23.y, blo.y);
            fma2(acc[3][2], a23.y, bhi.x); fma2(acc[3][3], a23.y, bhi.y);
            fma2(acc[4][0], a45.x, blo.x); fma2(acc[4][1], a45.x, blo.y);
            fma2(acc[4][2], a45.x, bhi.x); fma2(acc[4][3], a45.x, bhi.y);
            fma2(acc[5][0], a45.y, blo.x); fma2(acc[5][1], a45.y, blo.y);
            fma2(acc[5][2], a45.y, bhi.x); fma2(acc[5][3], a45.y, bhi.y);
            fma2(acc[6][0], a67.x, blo.x); fma2(acc[6][1], a67.x, blo.y);
            fma2(acc[6][2], a67.x, bhi.x); fma2(acc[6][3], a67.x, bhi.y);
            fma2(acc[7][0], a67.y, blo.x); fma2(acc[7][1], a67.y, blo.y);
            fma2(acc[7][2], a67.y, bhi.x); fma2(acc[7][3], a67.y, bhi.y);
        }
        int nb = buf ^ 1;
        sA[nb][akq + 0][2 * arow] = a_ld.x; sA[nb][akq + 0][2 * arow + 1] = a_ld.x;
        sA[nb][akq + 1][2 * arow] = a_ld.y; sA[nb][akq + 1][2 * arow + 1] = a_ld.y;
        sA[nb][akq + 2][2 * arow] = a_ld.z; sA[nb][akq + 2][2 * arow + 1] = a_ld.z;
        sA[nb][akq + 3][2 * arow] = a_ld.w; sA[nb][akq + 3][2 * arow + 1] = a_ld.w;
        *(float4*)(&sB[nb][bkr][bnq]) = b_ld;
        __syncthreads();
        buf = nb;
    }
    // last stage compute
#pragma unroll
    for (int k = 0; k < 8; k++) {
        ulonglong2 a01 = *(const ulonglong2*)(&sA[buf][k][(ty * 8 + 0) * 2]);
        ulonglong2 a23 = *(const ulonglong2*)(&sA[buf][k][(ty * 8 + 2) * 2]);
        ulonglong2 a45 = *(const ulonglong2*)(&sA[buf][k][(ty * 8 + 4) * 2]);
        ulonglong2 a67 = *(const ulonglong2*)(&sA[buf][k][(ty * 8 + 6) * 2]);
        ulonglong2 blo = *(const ulonglong2*)(&sB[buf][k][tx * 4]);
        ulonglong2 bhi = *(const ulonglong2*)(&sB[buf][k][64 + tx * 4]);
        fma2(acc[0][0], a01.x, blo.x); fma2(acc[0][1], a01.x, blo.y);
        fma2(acc[0][2], a01.x, bhi.x); fma2(acc[0][3], a01.x, bhi.y);
        fma2(acc[1][0], a01.y, blo.x); fma2(acc[1][1], a01.y, blo.y);
        fma2(acc[1][2], a01.y, bhi.x); fma2(acc[1][3], a01.y, bhi.y);
        fma2(acc[2][0], a23.x, blo.x); fma2(acc[2][1], a23.x, blo.y);
        fma2(acc[2][2], a23.x, bhi.x); fma2(acc[2][3], a23.x, bhi.y);
        fma2(acc[3][0], a23.y, blo.x); fma2(acc[3][1], a23.y, blo.y);
        fma2(acc[3][2], a23.y, bhi.x); fma2(acc[3][3], a23.y, bhi.y);
        fma2(acc[4][0], a45.x, blo.x); fma2(acc[4][1], a45.x, blo.y);
        fma2(acc[4][2], a45.x, bhi.x); fma2(acc[4][3], a45.x, bhi.y);
        fma2(acc[5][0], a45.y, blo.x); fma2(acc[5][1], a45.y, blo.y);
        fma2(acc[5][2], a45.y, bhi.x); fma2(acc[5][3], a45.y, bhi.y);
        fma2(acc[6][0], a67.x, blo.x); fma2(acc[6][1], a67.x, blo.y);
        fma2(acc[6][2], a67.x, bhi.x); fma2(acc[6][3], a67.x, bhi.y);
        fma2(acc[7][0], a67.y, blo.x); fma2(acc[7][1], a67.y, blo.y);
        fma2(acc[7][2], a67.y, bhi.x); fma2(acc[7][3], a67.y, bhi.y);
    }

    // ---- epilogue ----
    float bl0 = bias[c0 + tx * 4 + 0], bl1 = bias[c0 + tx * 4 + 1];
    float bl2 = bias[c0 + tx * 4 + 2], bl3 = bias[c0 + tx * 4 + 3];
    float bh0 = bias[c0 + 64 + tx * 4 + 0], bh1 = bias[c0 + 64 + tx * 4 + 1];
    float bh2 = bias[c0 + 64 + tx * 4 + 2], bh3 = bias[c0 + 64 + tx * 4 + 3];

#pragma unroll
    for (int i = 0; i < 8; i++) {
        int r = ty * 8 + i;
        float l0, l1, l2, l3, h0, h1, h2, h3;
        unpack2(acc[i][0], l0, l1);
        unpack2(acc[i][1], l2, l3);
        unpack2(acc[i][2], h0, h1);
        unpack2(acc[i][3], h2, h3);
        l0 = elu(l0 + bl0); l1 = elu(l1 + bl1); l2 = elu(l2 + bl2); l3 = elu(l3 + bl3);
        h0 = elu(h0 + bh0); h1 = elu(h1 + bh1); h2 = elu(h2 + bh2); h3 = elu(h3 + bh3);
        if (MSG) {
            float xlo = sXlo[r], xhi = sXhi[r];
            int d = sDst[r];
            if (d >= 0) {
                float* p = agg + (size_t)d * 64 + tx * 4;
                atomicAdd(p + 0, fmaf(xlo, l0, xhi * h0));
                atomicAdd(p + 1, fmaf(xlo, l1, xhi * h1));
                atomicAdd(p + 2, fmaf(xlo, l2, xhi * h2));
                atomicAdd(p + 3, fmaf(xlo, l3, xhi * h3));
            }
        } else {
            float* cp = C + (size_t)(e0 + r) * 1024 + c0;
            *(float4*)(cp + tx * 4) = make_float4(l0, l1, l2, l3);
            *(float4*)(cp + 64 + tx * 4) = make_float4(h0, h1, h2, h3);
        }
    }
}

// ---------------- launch ----------------
extern "C" void kernel_launch(void* const* d_in, const int* in_sizes, int n_in,
                              void* d_out, int out_size) {
    const float* x      = (const float*)d_in[0];
    const int*   ei     = (const int*)d_in[1];
    const float* attr   = (const float*)d_in[2];
    const float* enn_w1 = (const float*)d_in[3];
    const float* enn_b1 = (const float*)d_in[4];
    const float* enn_w2 = (const float*)d_in[5];
    const float* enn_b2 = (const float*)d_in[6];
    const float* enn_w3 = (const float*)d_in[7];
    const float* enn_b3 = (const float*)d_in[8];
    const float* root_w = (const float*)d_in[9];
    const float* root_b = (const float*)d_in[10];
    const float* gin_w1 = (const float*)d_in[11];
    const float* gin_b1 = (const float*)d_in[12];
    const float* gin_w2 = (const float*)d_in[13];
    const float* gin_b2 = (const float*)d_in[14];
    const float* gin_w3 = (const float*)d_in[15];
    const float* gin_b3 = (const float*)d_in[16];
    float* out = (float*)d_out;

    float *h1, *h2, *agg, *act, *nbr, *t1, *t2;
    cudaGetSymbolAddress((void**)&h1, g_h1);
    cudaGetSymbolAddress((void**)&h2, g_h2);
    cudaGetSymbolAddress((void**)&agg, g_agg);
    cudaGetSymbolAddress((void**)&act, g_act);
    cudaGetSymbolAddress((void**)&nbr, g_nbr);
    cudaGetSymbolAddress((void**)&t1, g_t1);
    cudaGetSymbolAddress((void**)&t2, g_t2);

    const int THREADS = 256;
    int gy_N = (NN + 63) / 64;

    // ---- Layer 0: NNConv ----
    // h1 = ELU(attr @ enn_w1 + b1)   [E,256]   (pad rows of g_h1 stay zero)
    k_gemm<1, 0><<<dim3(4, (NE + 63) / 64), THREADS>>>(attr, enn_w1, enn_b1, h1,
                                                       NE, 256, 16, nullptr, 0);
    // h2 = ELU(h1 @ enn_w2 + b2)     [NEP,1024] (pad rows computed from zeros: harmless)
    k_big<256, 0><<<dim3(8, NEP / 128), THREADS>>>(h1, enn_w2, enn_b2, h2,
                                                   nullptr, nullptr, nullptr);
    k_zero<<<(NN * 64 + THREADS - 1) / THREADS, THREADS>>>(agg, NN * 64);
    // fused: we = ELU(h2 @ enn_w3 + b3); msg = x_src . we; agg[dst] += msg
    k_big<1024, 1><<<dim3(8, NEP / 128), THREADS>>>(h2, enn_w3, enn_b3, nullptr,
                                                    x, ei, agg);
    k_combine0<<<(NN * 64 + THREADS - 1) / THREADS, THREADS>>>(x, root_w, root_b,
                                                               agg, out, act);

    // ---- Layers 1..3: GINConv ----
    for (int l = 0; l < 3; l++) {
        k_copy<<<(NN * 64 + THREADS - 1) / THREADS, THREADS>>>(nbr, act, NN * 64);
        k_scatter<<<(NE * 16 + THREADS - 1) / THREADS, THREADS>>>(act, ei, nbr);
        k_gemm<1, 0><<<dim3(4, gy_N), THREADS>>>(nbr, gin_w1 + (size_t)l * 64 * 256,
                                                 gin_b1 + l * 256, t1,
                                                 NN, 256, 64, nullptr, 0);
        k_gemm<1, 0><<<dim3(4, gy_N), THREADS>>>(t1, gin_w2 + (size_t)l * 256 * 256,
                                                 gin_b2 + l * 256, t2,
                                                 NN, 256, 256, nullptr, 0);
        k_gemm<0, 1><<<dim3(1, gy_N), THREADS>>>(t2, gin_w3 + (size_t)l * 256 * 64,
                                                 gin_b3 + l * 64, act,
                                                 NN, 64, 256, out, l + 1);
    }
}

// round 17
// speedup vs baseline: 2.1414x; 1.7553x over previous
#include <cuda_runtime.h>
#include <cuda_bf16.h>
#include <stdint.h>
#include <math.h>

#define NE  200000
#define NEP 200064              // 1563 * 128
#define NN  50000
#define ND  64
#define HID 256

// ---------------- scratch (device globals; zero-initialized) ----------------
__device__ float g_h1[(size_t)NEP * 256];              // fp32 h1
__device__ __nv_bfloat16 g_h1b[(size_t)NEP * 512];     // [hi(256) | lo(256)]
__device__ __nv_bfloat16 g_h2b[(size_t)NEP * 2048];    // [hi(1024) | lo(1024)]
__device__ __nv_bfloat16 g_w2t[(size_t)1024 * 512];    // W2^T: [n, hi(256)|lo(256)]
__device__ __nv_bfloat16 g_w3t[(size_t)1024 * 2048];   // W3^T: [n, hi(1024)|lo(1024)]
__device__ float g_agg[(size_t)NN * ND];
__device__ float g_act[(size_t)NN * ND];
__device__ float g_nbr[(size_t)NN * ND];
__device__ float g_t1[(size_t)NN * HID];
__device__ float g_t2[(size_t)NN * HID];

__device__ __forceinline__ float elu(float v) {
    return v > 0.f ? v : (__expf(v) - 1.f);
}
__device__ __forceinline__ uint32_t smem_u32(const void* p) {
    uint32_t a;
    asm("{ .reg .u64 t; cvta.to.shared.u64 t, %1; cvt.u32.u64 %0, t; }" : "=r"(a) : "l"(p));
    return a;
}
// ldmatrix x4 (sm_75+ baseline PTX — works on .target sm_103)
__device__ __forceinline__ void ldm4(uint32_t* r, uint32_t addr) {
    asm volatile("ldmatrix.sync.aligned.m8n8.x4.shared.b16 {%0,%1,%2,%3}, [%4];"
                 : "=r"(r[0]), "=r"(r[1]), "=r"(r[2]), "=r"(r[3]) : "r"(addr));
}
// mma.sync bf16 (sm_80+ baseline PTX)
__device__ __forceinline__ void mma_bf16(float* d, const uint32_t* a, uint32_t b0, uint32_t b1) {
    asm volatile(
        "mma.sync.aligned.m16n8k16.row.col.f32.bf16.bf16.f32 "
        "{%0,%1,%2,%3}, {%4,%5,%6,%7}, {%8,%9}, {%0,%1,%2,%3};"
        : "+f"(d[0]), "+f"(d[1]), "+f"(d[2]), "+f"(d[3])
        : "r"(a[0]), "r"(a[1]), "r"(a[2]), "r"(a[3]), "r"(b0), "r"(b1));
}

// ---------------- small utility kernels ----------------
__global__ void k_zero(float* __restrict__ p, int n) {
    int i = blockIdx.x * blockDim.x + threadIdx.x;
    if (i < n) p[i] = 0.f;
}
__global__ void k_copy(float* __restrict__ dst, const float* __restrict__ src, int n) {
    int i = blockIdx.x * blockDim.x + threadIdx.x;
    if (i < n) dst[i] = src[i];
}
__global__ void k_scatter(const float* __restrict__ act, const int* __restrict__ ei,
                          float* __restrict__ nbr) {
    int idx = blockIdx.x * blockDim.x + threadIdx.x;
    if (idx >= NE * 16) return;
    int e = idx >> 4, q = idx & 15;
    int s = ei[e];
    int d = ei[NE + e];
    float4 v = *(const float4*)(act + (size_t)s * 64 + q * 4);
    float* p = nbr + (size_t)d * 64 + q * 4;
    atomicAdd(p + 0, v.x);
    atomicAdd(p + 1, v.y);
    atomicAdd(p + 2, v.z);
    atomicAdd(p + 3, v.w);
}
__global__ void k_combine0(const float* __restrict__ x, const float* __restrict__ rw,
                           const float* __restrict__ rb, const float* __restrict__ agg,
                           float* __restrict__ out, float* __restrict__ act) {
    int idx = blockIdx.x * blockDim.x + threadIdx.x;
    if (idx >= NN * 64) return;
    int n = idx >> 6, o = idx & 63;
    const float* xr = x + (size_t)n * 16;
    float s = agg[idx] + rb[o];
#pragma unroll
    for (int k = 0; k < 16; k++) s += xr[k] * rw[k * 64 + o];
    out[(size_t)n * 256 + o * 4] = s;
    act[idx] = elu(s);
}
// fp32 -> bf16 hi/lo split of h1: [NEP,256] -> [NEP,512]
__global__ void k_cvt_h1(const float* __restrict__ h1, __nv_bfloat16* __restrict__ h1b) {
    int idx = blockIdx.x * blockDim.x + threadIdx.x;
    if (idx >= NEP * 256) return;
    int m = idx >> 8, k = idx & 255;
    float v = h1[idx];
    __nv_bfloat16 h = __float2bfloat16(v);
    h1b[(size_t)m * 512 + k] = h;
    h1b[(size_t)m * 512 + 256 + k] = __float2bfloat16(v - __bfloat162float(h));
}
// W[K,N] fp32 -> BT[N, 2K] bf16 (hi | lo)
__global__ void k_cvt_w(const float* __restrict__ W, __nv_bfloat16* __restrict__ BT,
                        int K, int N) {
    int idx = blockIdx.x * blockDim.x + threadIdx.x;
    if (idx >= K * N) return;
    int n = idx / K, k = idx - n * K;
    float v = W[(size_t)k * N + n];
    __nv_bfloat16 h = __float2bfloat16(v);
    BT[(size_t)n * 2 * K + k] = h;
    BT[(size_t)n * 2 * K + K + k] = __float2bfloat16(v - __bfloat162float(h));
}

// ---------------- generic tiled SGEMM (64x64x16) for h1 + GIN layers ----------------
template <int ACT, int EPI>
__global__ void __launch_bounds__(256)
k_gemm(const float* __restrict__ A, const float* __restrict__ B,
       const float* __restrict__ bias, float* __restrict__ C,
       int M, int N, int K, float* __restrict__ out2, int layer) {
    __shared__ float sA[16][68];
    __shared__ float sB[16][68];
    int tid = threadIdx.x;
    int tx = tid & 15, ty = tid >> 4;
    int m0 = blockIdx.y * 64, n0 = blockIdx.x * 64;
    int lr = tid >> 2, lc = tid & 3;
    int br = tid >> 4, bc = tid & 15;

    float acc[4][4] = {};
    for (int kc = 0; kc < K; kc += 16) {
        float4 av = make_float4(0.f, 0.f, 0.f, 0.f);
        if (m0 + lr < M)
            av = *(const float4*)(A + (size_t)(m0 + lr) * K + kc + lc * 4);
        float4 bv = *(const float4*)(B + (size_t)(kc + br) * N + n0 + bc * 4);
        __syncthreads();
        sA[lc * 4 + 0][lr] = av.x;
        sA[lc * 4 + 1][lr] = av.y;
        sA[lc * 4 + 2][lr] = av.z;
        sA[lc * 4 + 3][lr] = av.w;
        *(float4*)(&sB[br][bc * 4]) = bv;
        __syncthreads();
#pragma unroll
        for (int k = 0; k < 16; k++) {
            float4 a4 = *(const float4*)(&sA[k][ty * 4]);
            float4 b4 = *(const float4*)(&sB[k][tx * 4]);
            float a[4] = {a4.x, a4.y, a4.z, a4.w};
            float b[4] = {b4.x, b4.y, b4.z, b4.w};
#pragma unroll
            for (int i = 0; i < 4; i++)
#pragma unroll
                for (int j = 0; j < 4; j++) acc[i][j] = fmaf(a[i], b[j], acc[i][j]);
        }
    }
#pragma unroll
    for (int j = 0; j < 4; j++) {
        int n = n0 + tx * 4 + j;
        float bv = bias[n];
#pragma unroll
        for (int i = 0; i < 4; i++) {
            int m = m0 + ty * 4 + i;
            if (m < M) {
                float v = acc[i][j] + bv;
                if (EPI == 1) {
                    out2[(size_t)m * 256 + n * 4 + layer] = v;
                    C[(size_t)m * N + n] = elu(v);
                } else {
                    if (ACT == 1) v = elu(v);
                    C[(size_t)m * N + n] = v;
                }
            }
        }
    }
}

// ---------------- tensor-core big GEMM via mma.sync (3-term bf16 split) ----------------
// A: bf16 [NEP, 2*KSEG] (hi|lo), B: bf16 [1024, 2*KSEG] (hi|lo, B^T layout, k-contiguous).
// Tile 128x128, chunk K=64, 8 warps: warp tile 32(M) x 64(N), fp32 register accum.
// Terms: A_hi*B_hi + A_lo*B_hi + A_hi*B_lo.
// MSG=0: Cb[r][c]=bf16hi(ELU(acc+bias)), Cb[r][1024+c]=bf16lo.
// MSG=1: msg[r,o] = sum_g x[src[r], 2bx+g]*ELU(...); smem-merged, then atomicAdd agg[dst].
#define TS 72   // smem tile row stride in bf16 (144 B: conflict-free for ldmatrix)
template <int KSEG, int MSG>
__global__ void __launch_bounds__(256, 2)
k_mma(const __nv_bfloat16* __restrict__ A, const __nv_bfloat16* __restrict__ B,
      const float* __restrict__ bias, __nv_bfloat16* __restrict__ Cb,
      const float* __restrict__ x, const int* __restrict__ ei, float* __restrict__ agg) {
    const int AS = 2 * KSEG;   // row stride (bf16) of A and B
    __shared__ __align__(16) char smraw[2 * 128 * TS * 2];   // 36864 B
    __nv_bfloat16* sA = (__nv_bfloat16*)smraw;
    __nv_bfloat16* sB = (__nv_bfloat16*)(smraw + 128 * TS * 2);
    float* smsg = (float*)smraw;                              // reused post-mainloop (33792 B)
    __shared__ float sXw[2][128];
    __shared__ int sDst[128];

    int tid = threadIdx.x;
    int lane = tid & 31, warp = tid >> 5;
    int warpM = warp & 3, warpN = warp >> 2;
    int e0 = blockIdx.y * 128, c0 = blockIdx.x * 128;

    if (MSG) {
        if (tid < 128) {
            int e = e0 + tid;
            int s = 0, d = -1;
            if (e < NE) { s = ei[e]; d = ei[NE + e]; }
            float2 xv = *(const float2*)(x + (size_t)s * 16 + blockIdx.x * 2);
            sXw[0][tid] = xv.x;
            sXw[1][tid] = xv.y;
            sDst[tid] = d;
        }
    }

    float acc[2][8][4];
#pragma unroll
    for (int i = 0; i < 2; i++)
#pragma unroll
        for (int j = 0; j < 8; j++)
#pragma unroll
            for (int q = 0; q < 4; q++) acc[i][j][q] = 0.f;

    // ldmatrix base addresses (bytes)
    uint32_t a_addr = smem_u32(sA) + (uint32_t)(((warpM * 32 + (lane & 15)) * TS + (lane >> 4) * 8) * 2);
    uint32_t b_addr = smem_u32(sB) + (uint32_t)(((warpN * 64 + (lane & 15)) * TS + (lane >> 4) * 8) * 2);

    const int aoffs[3] = {0, KSEG, 0};
    const int boffs[3] = {0, 0, KSEG};

#pragma unroll 1
    for (int t = 0; t < 3; t++) {
        const __nv_bfloat16* Ab = A + (size_t)e0 * AS + aoffs[t];
        const __nv_bfloat16* Bb = B + (size_t)c0 * AS + boffs[t];
#pragma unroll 1
        for (int kc = 0; kc < KSEG; kc += 64) {
            __syncthreads();
#pragma unroll
            for (int u = 0; u < 4; u++) {
                int idx = u * 256 + tid;
                int row = idx >> 3, v = idx & 7;
                uint4 av = *(const uint4*)(Ab + (size_t)row * AS + kc + v * 8);
                uint4 bv = *(const uint4*)(Bb + (size_t)row * AS + kc + v * 8);
                *(uint4*)(sA + row * TS + v * 8) = av;
                *(uint4*)(sB + row * TS + v * 8) = bv;
            }
            __syncthreads();
#pragma unroll
            for (int k16 = 0; k16 < 64; k16 += 16) {
                uint32_t af[2][4], bfr[4][4];
                ldm4(af[0], a_addr + k16 * 2);
                ldm4(af[1], a_addr + (16 * TS + k16) * 2);
#pragma unroll
                for (int jj = 0; jj < 4; jj++)
                    ldm4(bfr[jj], b_addr + (jj * 16 * TS + k16) * 2);
#pragma unroll
                for (int i = 0; i < 2; i++)
#pragma unroll
                    for (int jj = 0; jj < 4; jj++) {
                        mma_bf16(acc[i][2 * jj + 0], af[i], bfr[jj][0], bfr[jj][2]);
                        mma_bf16(acc[i][2 * jj + 1], af[i], bfr[jj][1], bfr[jj][3]);
                    }
            }
        }
    }

    // ---- epilogue ----
    int tq = lane >> 2, tr = lane & 3;
    if (MSG) {
        __syncthreads();   // tiles dead; smsg reuses the space
        // phase 0: warpN==0 writes; phase 1: warpN==1 accumulates
        if (warpN == 0) {
#pragma unroll
            for (int i = 0; i < 2; i++) {
                int r0 = warpM * 32 + 16 * i + tq;
                float xw0 = sXw[0][r0], xw1 = sXw[0][r0 + 8];
#pragma unroll
                for (int j = 0; j < 8; j++) {
                    int o = 8 * j + 2 * tr;
                    float b0 = bias[c0 + o], b1 = bias[c0 + o + 1];
                    smsg[r0 * 66 + o]           = xw0 * elu(acc[i][j][0] + b0);
                    smsg[r0 * 66 + o + 1]       = xw0 * elu(acc[i][j][1] + b1);
                    smsg[(r0 + 8) * 66 + o]     = xw1 * elu(acc[i][j][2] + b0);
                    smsg[(r0 + 8) * 66 + o + 1] = xw1 * elu(acc[i][j][3] + b1);
                }
            }
        }
        __syncthreads();
        if (warpN == 1) {
#pragma unroll
            for (int i = 0; i < 2; i++) {
                int r0 = warpM * 32 + 16 * i + tq;
                float xw0 = sXw[1][r0], xw1 = sXw[1][r0 + 8];
#pragma unroll
                for (int j = 0; j < 8; j++) {
                    int o = 8 * j + 2 * tr;
                    float b0 = bias[c0 + 64 + o], b1 = bias[c0 + 64 + o + 1];
                    smsg[r0 * 66 + o]           += xw0 * elu(acc[i][j][0] + b0);
                    smsg[r0 * 66 + o + 1]       += xw0 * elu(acc[i][j][1] + b1);
                    smsg[(r0 + 8) * 66 + o]     += xw1 * elu(acc[i][j][2] + b0);
                    smsg[(r0 + 8) * 66 + o + 1] += xw1 * elu(acc[i][j][3] + b1);
                }
            }
        }
        __syncthreads();
        // flush: one atomic pass (merged groups)
        int r = tid >> 1, o0 = (tid & 1) * 32;
        int d = sDst[r];
        if (d >= 0) {
            float* p = agg + (size_t)d * 64 + o0;
            const float* mp = smsg + r * 66 + o0;
#pragma unroll
            for (int j = 0; j < 32; j++) atomicAdd(p + j, mp[j]);
        }
    } else {
#pragma unroll
        for (int i = 0; i < 2; i++) {
            int r0 = e0 + warpM * 32 + 16 * i + tq;
#pragma unroll
            for (int j = 0; j < 8; j++) {
                int c = c0 + warpN * 64 + 8 * j + 2 * tr;
                float b0 = bias[c], b1 = bias[c + 1];
                float va = elu(acc[i][j][0] + b0);
                float vb = elu(acc[i][j][1] + b1);
                float vc = elu(acc[i][j][2] + b0);
                float vd = elu(acc[i][j][3] + b1);
                __nv_bfloat16 ha = __float2bfloat16(va), hb = __float2bfloat16(vb);
                __nv_bfloat16 hc = __float2bfloat16(vc), hd = __float2bfloat16(vd);
                __nv_bfloat162 h01 = __halves2bfloat162(ha, hb);
                __nv_bfloat162 h23 = __halves2bfloat162(hc, hd);
                __nv_bfloat162 l01 = __halves2bfloat162(
                    __float2bfloat16(va - __bfloat162float(ha)),
                    __float2bfloat16(vb - __bfloat162float(hb)));
                __nv_bfloat162 l23 = __halves2bfloat162(
                    __float2bfloat16(vc - __bfloat162float(hc)),
                    __float2bfloat16(vd - __bfloat162float(hd)));
                *(__nv_bfloat162*)(Cb + (size_t)r0 * 2048 + c) = h01;
                *(__nv_bfloat162*)(Cb + (size_t)r0 * 2048 + 1024 + c) = l01;
                *(__nv_bfloat162*)(Cb + (size_t)(r0 + 8) * 2048 + c) = h23;
                *(__nv_bfloat162*)(Cb + (size_t)(r0 + 8) * 2048 + 1024 + c) = l23;
            }
        }
    }
}

// ---------------- launch ----------------
extern "C" void kernel_launch(void* const* d_in, const int* in_sizes, int n_in,
                              void* d_out, int out_size) {
    const float* x      = (const float*)d_in[0];
    const int*   ei     = (const int*)d_in[1];
    const float* attr   = (const float*)d_in[2];
    const float* enn_w1 = (const float*)d_in[3];
    const float* enn_b1 = (const float*)d_in[4];
    const float* enn_w2 = (const float*)d_in[5];
    const float* enn_b2 = (const float*)d_in[6];
    const float* enn_w3 = (const float*)d_in[7];
    const float* enn_b3 = (const float*)d_in[8];
    const float* root_w = (const float*)d_in[9];
    const float* root_b = (const float*)d_in[10];
    const float* gin_w1 = (const float*)d_in[11];
    const float* gin_b1 = (const float*)d_in[12];
    const float* gin_w2 = (const float*)d_in[13];
    const float* gin_b2 = (const float*)d_in[14];
    const float* gin_w3 = (const float*)d_in[15];
    const float* gin_b3 = (const float*)d_in[16];
    float* out = (float*)d_out;

    float *h1, *agg, *act, *nbr, *t1, *t2;
    __nv_bfloat16 *h1b, *h2b, *w2t, *w3t;
    cudaGetSymbolAddress((void**)&h1, g_h1);
    cudaGetSymbolAddress((void**)&h1b, g_h1b);
    cudaGetSymbolAddress((void**)&h2b, g_h2b);
    cudaGetSymbolAddress((void**)&w2t, g_w2t);
    cudaGetSymbolAddress((void**)&w3t, g_w3t);
    cudaGetSymbolAddress((void**)&agg, g_agg);
    cudaGetSymbolAddress((void**)&act, g_act);
    cudaGetSymbolAddress((void**)&nbr, g_nbr);
    cudaGetSymbolAddress((void**)&t1, g_t1);
    cudaGetSymbolAddress((void**)&t2, g_t2);

    const int THREADS = 256;
    int gy_N = (NN + 63) / 64;

    // weight transposes + bf16 hi/lo splits
    k_cvt_w<<<(256 * 1024 + THREADS - 1) / THREADS, THREADS>>>(enn_w2, w2t, 256, 1024);
    k_cvt_w<<<(1024 * 1024 + THREADS - 1) / THREADS, THREADS>>>(enn_w3, w3t, 1024, 1024);

    // h1 = ELU(attr @ enn_w1 + b1) (fp32), then split to bf16 hi/lo
    k_gemm<1, 0><<<dim3(4, (NE + 63) / 64), THREADS>>>(attr, enn_w1, enn_b1, h1,
                                                       NE, 256, 16, nullptr, 0);
    k_cvt_h1<<<(NEP * 256 + THREADS - 1) / THREADS, THREADS>>>(h1, h1b);

    // h2 = ELU(h1 @ enn_w2 + b2) on tensor cores (mma.sync) -> bf16 hi/lo
    k_mma<256, 0><<<dim3(8, NEP / 128), THREADS>>>(h1b, w2t, enn_b2, h2b,
                                                   nullptr, nullptr, nullptr);
    k_zero<<<(NN * 64 + THREADS - 1) / THREADS, THREADS>>>(agg, NN * 64);
    // fused NNConv message: we = ELU(h2 @ enn_w3 + b3); msg = x_src . we; agg[dst] += msg
    k_mma<1024, 1><<<dim3(8, NEP / 128), THREADS>>>(h2b, w3t, enn_b3, nullptr,
                                                    x, ei, agg);
    k_combine0<<<(NN * 64 + THREADS - 1) / THREADS, THREADS>>>(x, root_w, root_b,
                                                               agg, out, act);

    // ---- Layers 1..3: GINConv ----
    for (int l = 0; l < 3; l++) {
        k_copy<<<(NN * 64 + THREADS - 1) / THREADS, THREADS>>>(nbr, act, NN * 64);
        k_scatter<<<(NE * 16 + THREADS - 1) / THREADS, THREADS>>>(act, ei, nbr);
        k_gemm<1, 0><<<dim3(4, gy_N), THREADS>>>(nbr, gin_w1 + (size_t)l * 64 * 256,
                                                 gin_b1 + l * 256, t1,
                                                 NN, 256, 64, nullptr, 0);
        k_gemm<1, 0><<<dim3(4, gy_N), THREADS>>>(t1, gin_w2 + (size_t)l * 256 * 256,
                                                 gin_b2 + l * 256, t2,
                                                 NN, 256, 256, nullptr, 0);
        k_gemm<0, 1><<<dim3(1, gy_N), THREADS>>>(t2, gin_w3 + (size_t)l * 256 * 64,
                                                 gin_b3 + l * 64, act,
                                                 NN, 64, 256, out, l + 1);
    }
}